// round 10
// baseline (speedup 1.0000x reference)
#include <cuda_runtime.h>
#include <math.h>
#include <float.h>
#include <stdint.h>

// ---------------- problem constants ----------------
#define BEAM   5
#define TOPK   5
#define VOCAB  128000
#define HIST   511
#define NUM_KV 16
#define HEADS  8
#define SEQ    2048
#define HDIM   128

#define SM_CHUNKS 125                // stage-1 chunks per beam
#define TPB_SM    256
#define NWARPS_B  (SM_CHUNKS*8)      // 1000 warp-slots per beam (each covers 128 elems)

#define NEG_SENTINEL (-FLT_MAX)      // finite sentinel: avoids (-INF)-(-INF)=NaN in merges

#define KV_ROW_ELEMS  (HEADS*SEQ*HDIM)          // 2,097,152 floats per (kv,beam)
#define KV_ROW4       (KV_ROW_ELEMS/4)          // 524,288 float4
#define KV_TOTAL      (NUM_KV*BEAM*KV_ROW_ELEMS)

// output layout (floats), in reference tuple order
#define OFF_SAVE   (KV_TOTAL)
#define OFF_RP     (OFF_SAVE + BEAM*(HIST+1))
#define OFF_PROB   (OFF_RP + BEAM*VOCAB)
#define OFF_TOK    (OFF_PROB + BEAM)
#define OFF_MAXIDX (OFF_TOK + BEAM)

// ---------------- device scratch ----------------
__device__ float g_wm[BEAM*NWARPS_B];    // per-warp max
__device__ float g_ws[BEAM*NWARPS_B];    // per-warp sum-exp (rel. to g_wm)
__device__ int   g_beam_index[BEAM];
__device__ int   g_token[BEAM];
__device__ unsigned int g_counter = 0;   // ticket for last-block combine (reset each run)

// ---------------- top-5 helpers (descending, ties -> lower index) ----------------
__device__ __forceinline__ void top5_insert(float* v, int* ix, float val, int idx) {
    if (val < v[TOPK-1]) return;
    if (val == v[TOPK-1] && idx >= ix[TOPK-1]) return;
    int p = TOPK - 1;
    #pragma unroll
    for (int q = TOPK - 1; q > 0; q--) {
        if (val > v[q-1] || (val == v[q-1] && idx < ix[q-1])) {
            v[q] = v[q-1]; ix[q] = ix[q-1]; p = q - 1;
        } else break;
    }
    v[p] = val; ix[p] = idx;
}

__device__ __forceinline__ void warp_merge(float* v, int* ix, float& m, float& s) {
    #pragma unroll
    for (int off = 16; off > 0; off >>= 1) {
        float pv[TOPK]; int pi[TOPK];
        #pragma unroll
        for (int j = 0; j < TOPK; j++) {
            pv[j] = __shfl_down_sync(0xffffffffu, v[j],  off);
            pi[j] = __shfl_down_sync(0xffffffffu, ix[j], off);
        }
        float pm = __shfl_down_sync(0xffffffffu, m, off);
        float ps = __shfl_down_sync(0xffffffffu, s, off);
        #pragma unroll
        for (int j = 0; j < TOPK; j++) top5_insert(v, ix, pv[j], pi[j]);
        float nm = fmaxf(m, pm);
        s = s * __expf(m - nm) + ps * __expf(pm - nm);   // finite sentinels, no NaN
        m = nm;
    }
}

// ---------------- kernel 1: per-warp (max,sumexp); last block does exact top-k ----------------
__global__ void __launch_bounds__(TPB_SM)
softmax_topk_kernel(const float4* __restrict__ logits, const float4* __restrict__ rpen,
                    const float* __restrict__ prev_prob,
                    float* __restrict__ out_prob,
                    float* __restrict__ out_tok,
                    float* __restrict__ out_maxidx) {
    const int c = blockIdx.x;            // chunk 0..124
    const int b = blockIdx.y;            // beam
    const int t = threadIdx.x;
    const int warp = t >> 5;
    const int lane = t & 31;

    // one float4 of logits*rp per thread
    const int f4i = c * TPB_SM + t;
    float4 xl = __ldg(logits + (size_t)b * (VOCAB/4) + f4i);
    float4 xr = __ldg(rpen   + (size_t)b * (VOCAB/4) + f4i);
    float x0 = xl.x * xr.x, x1 = xl.y * xr.y, x2 = xl.z * xr.z, x3 = xl.w * xr.w;

    float m = fmaxf(fmaxf(x0, x1), fmaxf(x2, x3));
    float s = __expf(x0-m) + __expf(x1-m) + __expf(x2-m) + __expf(x3-m);

    // warp-reduce (m,s); reduced m IS the warp max
    #pragma unroll
    for (int off = 16; off > 0; off >>= 1) {
        float pm = __shfl_down_sync(0xffffffffu, m, off);
        float ps = __shfl_down_sync(0xffffffffu, s, off);
        float nm = fmaxf(m, pm);
        s = s * __expf(m - nm) + ps * __expf(pm - nm);
        m = nm;
    }
    if (lane == 0) {
        const int ws_idx = b * NWARPS_B + c * 8 + warp;   // warp-slot
        g_wm[ws_idx] = m;
        g_ws[ws_idx] = s;
        __threadfence();
    }
    __syncthreads();

    // ticket: last block combines
    __shared__ int s_last;
    if (t == 0) {
        unsigned int tk = atomicAdd(&g_counter, 1u);
        s_last = (tk == (unsigned)(SM_CHUNKS*BEAM - 1));
    }
    __syncthreads();
    if (!s_last) return;

    // ================= combine (last block; warp w handles beam w) =================
    __shared__ float s_cur[BEAM*TOPK];
    __shared__ int   s_ctok[BEAM*TOPK];

    if (warp < BEAM) {
        const int bb = warp;

        float v[TOPK]; int ix[TOPK];
        #pragma unroll
        for (int j = 0; j < TOPK; j++) { v[j] = NEG_SENTINEL; ix[j] = 0x7FFFFFFF; }
        float cm = NEG_SENTINEL, cs = 0.0f;
        for (int i = lane; i < 1024; i += 32) {          // 32 iters, pad beyond 1000
            float pm = NEG_SENTINEL, ps = 0.0f;
            if (i < NWARPS_B) { pm = g_wm[bb*NWARPS_B + i]; ps = g_ws[bb*NWARPS_B + i]; }
            float nm = fmaxf(cm, pm);
            cs = cs * __expf(cm - nm) + ps * __expf(pm - nm);
            cm = nm;
            top5_insert(v, ix, pm, i);
        }
        warp_merge(v, ix, cm, cs);                       // lane0: beam (m,s) + top-5 slots

        float lse = cm + logf(cs);
        lse = __shfl_sync(0xffffffffu, lse, 0);
        int slots[TOPK];
        #pragma unroll
        for (int j = 0; j < TOPK; j++) slots[j] = __shfl_sync(0xffffffffu, ix[j], 0);

        // rescan the 5 selected warp-slots (5*128 elements) for exact top-5
        float tv[TOPK]; int ti[TOPK];
        #pragma unroll
        for (int j = 0; j < TOPK; j++) { tv[j] = NEG_SENTINEL; ti[j] = 0x7FFFFFFF; }
        #pragma unroll
        for (int j = 0; j < TOPK; j++) {
            const int ws = slots[j];                     // 0..999, distinct
            const int f4 = ws * 32 + lane;
            float4 yl = __ldg(logits + (size_t)bb * (VOCAB/4) + f4);
            float4 yr = __ldg(rpen   + (size_t)bb * (VOCAB/4) + f4);
            const int e0 = f4 * 4;
            top5_insert(tv, ti, yl.x * yr.x, e0 + 0);
            top5_insert(tv, ti, yl.y * yr.y, e0 + 1);
            top5_insert(tv, ti, yl.z * yr.z, e0 + 2);
            top5_insert(tv, ti, yl.w * yr.w, e0 + 3);
        }
        float dm = NEG_SENTINEL, ds = 0.0f;
        warp_merge(tv, ti, dm, ds);

        if (lane == 0) {
            float pp = prev_prob[bb];
            #pragma unroll
            for (int j = 0; j < TOPK; j++) {
                s_cur[bb*TOPK + j]  = tv[j] - lse + pp;
                s_ctok[bb*TOPK + j] = ti[j];
            }
        }
    }
    __syncthreads();

    if (t == 0) {
        bool used[BEAM*TOPK];
        #pragma unroll
        for (int i = 0; i < BEAM*TOPK; i++) used[i] = false;
        for (int k = 0; k < BEAM; k++) {
            int best = 0; float bv = -INFINITY;
            for (int i = 0; i < BEAM*TOPK; i++) {
                if (!used[i] && s_cur[i] > bv) { bv = s_cur[i]; best = i; }  // lowest idx on ties
            }
            used[best] = true;
            int bi  = best / TOPK;
            int tok = s_ctok[best];
            g_beam_index[k] = bi;
            g_token[k]      = tok;
            out_prob[k]     = bv;
            out_tok[k]      = (float)tok;
            if (k == 0) out_maxidx[0] = (float)tok;
        }
        g_counter = 0;   // reset for next graph replay (deterministic)
        __threadfence();
    }
}

// ---------------- kernel 2: gather with STRUCTURAL read-dedup + uniform stores ----------------
// Block = (kv, 256-float4 chunk). It serves ALL 5 destination beams:
//   - loads the <=5 DISTINCT source values once each (block-uniform dup detection)
//   - stores 5 copies (one per dest) -- uniform 5 STG.128/thread in every block.
// Every source address is read exactly once per replay => reads = unique_beams * 128MB
// by construction, at any occupancy. __ldcs: no reuse exists, keep L2 for writes.
struct KvPtrs { const float4* p[NUM_KV]; };

#define TPB        256
#define KV_CHUNKS  (KV_ROW4/TPB)         // 2048 chunks per kv
#define RP_F4      (BEAM*VOCAB/4)        // 160000
#define RP_BLOCKS  ((RP_F4 + TPB - 1)/TPB)           // 625
#define SAVE_BLOCKS ((BEAM*(HIST+1) + TPB - 1)/TPB)  // 10

__global__ void __launch_bounds__(TPB)
gather_fused_kernel(KvPtrs kp,
                    const float* __restrict__ rpen,
                    const int*   __restrict__ save_id,
                    const float* __restrict__ pen,
                    float4* __restrict__ out) {
    const int kv = blockIdx.y;

    if (kv < NUM_KV) {
        __shared__ int s_bi[BEAM];
        if (threadIdx.x < BEAM) s_bi[threadIdx.x] = g_beam_index[threadIdx.x];
        __syncthreads();

        const int j = blockIdx.x * TPB + threadIdx.x;    // 0..524287
        const float4* __restrict__ base = kp.p[kv];

        // load distinct sources once; copy registers for duplicate sources
        float4 v[BEAM];
        #pragma unroll
        for (int d = 0; d < BEAM; d++) {
            const int bi = s_bi[d];
            bool dup = false;
            #pragma unroll
            for (int e = 0; e < d; e++) {
                if (s_bi[e] == bi && !dup) { v[d] = v[e]; dup = true; }
            }
            if (!dup) v[d] = __ldcs(base + (size_t)bi * KV_ROW4 + j);
        }

        // uniform stores: 5 per thread, one per dest beam
        float4* __restrict__ dst = out + (size_t)kv * BEAM * KV_ROW4 + j;
        #pragma unroll
        for (int d = 0; d < BEAM; d++)
            __stcs(dst + (size_t)d * KV_ROW4, v[d]);
        return;
    }

    // ---- tail row: repeat_penalty + save_id ----
    if (blockIdx.x < RP_BLOCKS) {
        int t = blockIdx.x * TPB + threadIdx.x;
        if (t >= RP_F4) return;
        int b  = t / (VOCAB/4);
        int v4 = t - b * (VOCAB/4);
        int bi = g_beam_index[b];
        float4 x = __ldcg((const float4*)rpen + (size_t)bi * (VOCAB/4) + v4);
        int tok = g_token[b];
        if ((tok >> 2) == v4) {
            float p = pen[0];
            ((float*)&x)[tok & 3] *= p;
        }
        float* o = (float*)out + OFF_RP;
        ((float4*)o)[t] = x;
        return;
    }

    if (blockIdx.x < RP_BLOCKS + SAVE_BLOCKS) {
        int t = (blockIdx.x - RP_BLOCKS) * TPB + threadIdx.x;
        if (t >= BEAM * (HIST + 1)) return;
        int b = t / (HIST + 1);
        int j = t - b * (HIST + 1);
        int bi = g_beam_index[b];
        float* o = (float*)out + OFF_SAVE;
        o[t] = (j < HIST) ? (float)save_id[bi * HIST + j] : (float)g_token[b];
    }
}

// ---------------- launch ----------------
extern "C" void kernel_launch(void* const* d_in, const int* in_sizes, int n_in,
                              void* d_out, int out_size) {
    (void)in_sizes; (void)n_in; (void)out_size;

    const int*   save_id = (const int*)  d_in[16];
    const float* rpen    = (const float*)d_in[17];
    const float* prev    = (const float*)d_in[18];
    // d_in[19] = batch_indices (arange, identity — unused)
    const float* logits  = (const float*)d_in[20];
    const float* pen     = (const float*)d_in[21];
    float* out = (float*)d_out;

    softmax_topk_kernel<<<dim3(SM_CHUNKS, BEAM), TPB_SM>>>(
        (const float4*)logits, (const float4*)rpen, prev,
        out + OFF_PROB, out + OFF_TOK, out + OFF_MAXIDX);

    KvPtrs kp;
    for (int i = 0; i < NUM_KV; i++) kp.p[i] = (const float4*)d_in[i];
    dim3 grid(KV_CHUNKS, NUM_KV + 1);    // 2048 x 17; tail row covers rp+save
    gather_fused_kernel<<<grid, TPB>>>(kp, rpen, save_id, pen, (float4*)out);
}

// round 11
// speedup vs baseline: 1.1214x; 1.1214x over previous
#include <cuda_runtime.h>
#include <math.h>
#include <float.h>
#include <stdint.h>

// ---------------- problem constants ----------------
#define BEAM   5
#define TOPK   5
#define VOCAB  128000
#define HIST   511
#define NUM_KV 16
#define HEADS  8
#define SEQ    2048
#define HDIM   128

#define TPB       256
#define SM_CHUNKS 125                 // stage-1 chunks per beam
#define NWARPS_B  (SM_CHUNKS*8)       // 1000 warp-slots per beam (128 elems each)

#define NEG_SENTINEL (-FLT_MAX)

#define KV_ROW_ELEMS  (HEADS*SEQ*HDIM)          // 2,097,152 floats per (kv,beam)
#define KV_ROW4       (KV_ROW_ELEMS/4)          // 524,288 float4
#define KV_TOTAL      (NUM_KV*BEAM*KV_ROW_ELEMS)

// output layout (floats), in reference tuple order
#define OFF_SAVE   (KV_TOTAL)
#define OFF_RP     (OFF_SAVE + BEAM*(HIST+1))
#define OFF_PROB   (OFF_RP + BEAM*VOCAB)
#define OFF_TOK    (OFF_PROB + BEAM)
#define OFF_MAXIDX (OFF_TOK + BEAM)

// ---------------- block ranges (1D fused grid) ----------------
#define SM_BLOCKS   (SM_CHUNKS*BEAM)            // 625 producers (scheduled first)
#define RP_F4       (BEAM*VOCAB/4)              // 160000 (= 625*256 exactly)
#define RP_BLOCKS   (RP_F4/TPB)                 // 625
#define SAVE_ELEMS  (BEAM*(HIST+1))             // 2560 (= 10*256 exactly)
#define SAVE_BLOCKS (SAVE_ELEMS/TPB)            // 10
#define KV_BASE     (SM_BLOCKS + RP_BLOCKS + SAVE_BLOCKS)   // 1260
#define KV_BLOCKS   (NUM_KV*BEAM*256)           // 20480 (R5 layout: 256 x-blocks/row)
#define TOTAL_BLKS  (KV_BASE + KV_BLOCKS)       // 21740
#define NCONS       (RP_BLOCKS + SAVE_BLOCKS + KV_BLOCKS)   // 21115 consumers

// ---------------- device scratch ----------------
__device__ float g_wm[BEAM*NWARPS_B];
__device__ float g_ws[BEAM*NWARPS_B];
__device__ int   g_beam_index[BEAM];
__device__ int   g_token[BEAM];
__device__ unsigned int g_counter = 0;   // producer ticket (reset by combine)
__device__ unsigned int g_done    = 0;   // consumer ticket (reset by last consumer)
__device__ int          g_flag    = 0;   // results-ready flag (reset by last consumer)

// ---------------- top-5 helpers (descending, ties -> lower index) ----------------
__device__ __forceinline__ void top5_insert(float* v, int* ix, float val, int idx) {
    if (val < v[TOPK-1]) return;
    if (val == v[TOPK-1] && idx >= ix[TOPK-1]) return;
    int p = TOPK - 1;
    #pragma unroll
    for (int q = TOPK - 1; q > 0; q--) {
        if (val > v[q-1] || (val == v[q-1] && idx < ix[q-1])) {
            v[q] = v[q-1]; ix[q] = ix[q-1]; p = q - 1;
        } else break;
    }
    v[p] = val; ix[p] = idx;
}

__device__ __forceinline__ void warp_merge(float* v, int* ix, float& m, float& s) {
    #pragma unroll
    for (int off = 16; off > 0; off >>= 1) {
        float pv[TOPK]; int pi[TOPK];
        #pragma unroll
        for (int j = 0; j < TOPK; j++) {
            pv[j] = __shfl_down_sync(0xffffffffu, v[j],  off);
            pi[j] = __shfl_down_sync(0xffffffffu, ix[j], off);
        }
        float pm = __shfl_down_sync(0xffffffffu, m, off);
        float ps = __shfl_down_sync(0xffffffffu, s, off);
        #pragma unroll
        for (int j = 0; j < TOPK; j++) top5_insert(v, ix, pv[j], pi[j]);
        float nm = fmaxf(m, pm);
        s = s * __expf(m - nm) + ps * __expf(pm - nm);
        m = nm;
    }
}

// ---------------- the ONE fused kernel ----------------
struct KvPtrs { const float4* p[NUM_KV]; };

__global__ void __launch_bounds__(TPB, 6)
fused_beam_kernel(KvPtrs kp,
                  const float4* __restrict__ logits, const float4* __restrict__ rpen4,
                  const float*  __restrict__ prev_prob,
                  const int*    __restrict__ save_id,
                  const float*  __restrict__ pen,
                  float4* __restrict__ out) {
    const int bid  = blockIdx.x;
    const int t    = threadIdx.x;
    const int warp = t >> 5;
    const int lane = t & 31;

    // ====================== PRODUCERS: softmax stage-1 + combine ======================
    if (bid < SM_BLOCKS) {
        const int b = bid / SM_CHUNKS;     // beam
        const int c = bid % SM_CHUNKS;     // chunk

        const int f4i = c * TPB + t;
        float4 xl = __ldg(logits + (size_t)b * (VOCAB/4) + f4i);
        float4 xr = __ldg(rpen4  + (size_t)b * (VOCAB/4) + f4i);
        float x0 = xl.x * xr.x, x1 = xl.y * xr.y, x2 = xl.z * xr.z, x3 = xl.w * xr.w;

        float m = fmaxf(fmaxf(x0, x1), fmaxf(x2, x3));
        float s = __expf(x0-m) + __expf(x1-m) + __expf(x2-m) + __expf(x3-m);

        #pragma unroll
        for (int off = 16; off > 0; off >>= 1) {
            float pm = __shfl_down_sync(0xffffffffu, m, off);
            float ps = __shfl_down_sync(0xffffffffu, s, off);
            float nm = fmaxf(m, pm);
            s = s * __expf(m - nm) + ps * __expf(pm - nm);
            m = nm;
        }
        if (lane == 0) {
            const int ws_idx = b * NWARPS_B + c * 8 + warp;
            g_wm[ws_idx] = m;
            g_ws[ws_idx] = s;
        }
        __syncthreads();

        __shared__ int s_last;
        if (t == 0) {
            __threadfence();
            unsigned int tk = atomicAdd(&g_counter, 1u);
            s_last = (tk == (unsigned)(SM_BLOCKS - 1));
        }
        __syncthreads();
        if (!s_last) return;

        // -------- combine (last producer block; warp w handles beam w) --------
        __shared__ float s_cur[BEAM*TOPK];
        __shared__ int   s_ctok[BEAM*TOPK];

        if (warp < BEAM) {
            const int bb = warp;
            float v[TOPK]; int ix[TOPK];
            #pragma unroll
            for (int j = 0; j < TOPK; j++) { v[j] = NEG_SENTINEL; ix[j] = 0x7FFFFFFF; }
            float cm = NEG_SENTINEL, cs = 0.0f;
            for (int i = lane; i < 1024; i += 32) {
                float pm = NEG_SENTINEL, ps = 0.0f;
                if (i < NWARPS_B) { pm = g_wm[bb*NWARPS_B + i]; ps = g_ws[bb*NWARPS_B + i]; }
                float nm = fmaxf(cm, pm);
                cs = cs * __expf(cm - nm) + ps * __expf(pm - nm);
                cm = nm;
                top5_insert(v, ix, pm, i);
            }
            warp_merge(v, ix, cm, cs);

            float lse = cm + logf(cs);
            lse = __shfl_sync(0xffffffffu, lse, 0);
            int slots[TOPK];
            #pragma unroll
            for (int j = 0; j < TOPK; j++) slots[j] = __shfl_sync(0xffffffffu, ix[j], 0);

            float tv[TOPK]; int ti[TOPK];
            #pragma unroll
            for (int j = 0; j < TOPK; j++) { tv[j] = NEG_SENTINEL; ti[j] = 0x7FFFFFFF; }
            #pragma unroll
            for (int j = 0; j < TOPK; j++) {
                const int ws = slots[j];
                const int f4 = ws * 32 + lane;
                float4 yl = __ldg(logits + (size_t)bb * (VOCAB/4) + f4);
                float4 yr = __ldg(rpen4  + (size_t)bb * (VOCAB/4) + f4);
                const int e0 = f4 * 4;
                top5_insert(tv, ti, yl.x * yr.x, e0 + 0);
                top5_insert(tv, ti, yl.y * yr.y, e0 + 1);
                top5_insert(tv, ti, yl.z * yr.z, e0 + 2);
                top5_insert(tv, ti, yl.w * yr.w, e0 + 3);
            }
            float dm = NEG_SENTINEL, ds = 0.0f;
            warp_merge(tv, ti, dm, ds);

            if (lane == 0) {
                float pp = prev_prob[bb];
                #pragma unroll
                for (int j = 0; j < TOPK; j++) {
                    s_cur[bb*TOPK + j]  = tv[j] - lse + pp;
                    s_ctok[bb*TOPK + j] = ti[j];
                }
            }
        }
        __syncthreads();

        if (t == 0) {
            bool used[BEAM*TOPK];
            #pragma unroll
            for (int i = 0; i < BEAM*TOPK; i++) used[i] = false;
            float* out_prob   = (float*)out + OFF_PROB;
            float* out_tok    = (float*)out + OFF_TOK;
            float* out_maxidx = (float*)out + OFF_MAXIDX;
            for (int k = 0; k < BEAM; k++) {
                int best = 0; float bv = -INFINITY;
                for (int i = 0; i < BEAM*TOPK; i++) {
                    if (!used[i] && s_cur[i] > bv) { bv = s_cur[i]; best = i; }
                }
                used[best] = true;
                int bi  = best / TOPK;
                int tok = s_ctok[best];
                g_beam_index[k] = bi;
                g_token[k]      = tok;
                out_prob[k]     = bv;
                out_tok[k]      = (float)tok;
                if (k == 0) out_maxidx[0] = (float)tok;
            }
            g_counter = 0;                       // reset producer ticket
            __threadfence();                     // publish results before flag
            atomicExch(&g_flag, 1);              // release
        }
        return;
    }

    // ====================== CONSUMERS: spin for results ======================
    if (t == 0) {
        while (*(volatile int*)&g_flag == 0) __nanosleep(64);
        __threadfence();                         // acquire
        // consumer ticket: count==NCONS only after ALL consumers passed the spin
        unsigned int d = atomicAdd(&g_done, 1u);
        if (d == (unsigned)(NCONS - 1)) {        // last consumer resets for next replay
            g_done = 0;
            g_flag = 0;
            __threadfence();
        }
    }
    __syncthreads();

    if (bid >= KV_BASE) {
        // ---- KV copy (EXACT R5 layout): row = kv*BEAM+b, 256 x-blocks/row ----
        const int r   = (bid - KV_BASE) >> 8;
        const int x   = (bid - KV_BASE) & 255;
        const int kv  = r / BEAM;
        const int b   = r - kv * BEAM;
        const int bi  = g_beam_index[b];

        const float4* __restrict__ src = kp.p[kv] + (size_t)bi * KV_ROW4;
        float4* __restrict__ dst = out + ((size_t)kv * BEAM + b) * KV_ROW4;

        const int j0 = x * TPB + t;              // 0..65535
        float4 vals[8];
        #pragma unroll
        for (int k = 0; k < 8; k++) vals[k] = __ldcg(src + j0 + k * 65536);
        #pragma unroll
        for (int k = 0; k < 8; k++) __stcs(dst + j0 + k * 65536, vals[k]);
        return;
    }

    if (bid < SM_BLOCKS + RP_BLOCKS) {
        // ---- repeat_penalty gather (float4) + token penalty ----
        int i  = (bid - SM_BLOCKS) * TPB + t;    // 0..159999 (exact)
        int b  = i / (VOCAB/4);
        int v4 = i - b * (VOCAB/4);
        int bi = g_beam_index[b];
        float4 xv = __ldcg(rpen4 + (size_t)bi * (VOCAB/4) + v4);
        int tok = g_token[b];
        if ((tok >> 2) == v4) {
            float p = pen[0];
            ((float*)&xv)[tok & 3] *= p;
        }
        float* o = (float*)out + OFF_RP;
        ((float4*)o)[i] = xv;
        return;
    }

    // ---- save_id gather + token append ----
    {
        int i = (bid - SM_BLOCKS - RP_BLOCKS) * TPB + t;   // 0..2559 (exact)
        int b = i / (HIST + 1);
        int j = i - b * (HIST + 1);
        int bi = g_beam_index[b];
        float* o = (float*)out + OFF_SAVE;
        o[i] = (j < HIST) ? (float)save_id[bi * HIST + j] : (float)g_token[b];
    }
}

// ---------------- launch ----------------
extern "C" void kernel_launch(void* const* d_in, const int* in_sizes, int n_in,
                              void* d_out, int out_size) {
    (void)in_sizes; (void)n_in; (void)out_size;

    const int*   save_id = (const int*)  d_in[16];
    const float* rpen    = (const float*)d_in[17];
    const float* prev    = (const float*)d_in[18];
    // d_in[19] = batch_indices (arange, identity — unused)
    const float* logits  = (const float*)d_in[20];
    const float* pen     = (const float*)d_in[21];

    KvPtrs kp;
    for (int i = 0; i < NUM_KV; i++) kp.p[i] = (const float4*)d_in[i];

    fused_beam_kernel<<<TOTAL_BLKS, TPB>>>(
        kp, (const float4*)logits, (const float4*)rpen, prev,
        save_id, pen, (float4*)d_out);
}